// round 5
// baseline (speedup 1.0000x reference)
#include <cuda_runtime.h>
#include <math.h>

// Problem constants
#define B_ 4
#define L_ 512
#define M_ 2048
#define D_ 1024
#define H_ 8
#define K_ 128
#define W_ 2560

// -------- scratch (device globals; no allocation allowed) --------
__device__ float g_xt[(size_t)B_ * L_ * D_];
__device__ float g_q [(size_t)B_ * L_ * D_];
__device__ float g_k [(size_t)B_ * L_ * D_];
__device__ float g_v [(size_t)B_ * L_ * D_];
__device__ float g_sin[(size_t)W_ * D_];
__device__ float g_r [(size_t)W_ * D_];
__device__ float g_corr[(size_t)H_ * W_];           // (xl_v - xl_u) . R[row]
__device__ float g_wv[(size_t)B_ * L_ * D_];

// ---------------- helpers ----------------
__device__ __forceinline__ unsigned tf32cvt(float f) {
    unsigned r;
    asm("cvt.rna.tf32.f32 %0, %1;" : "=r"(r) : "f"(f));
    return r;
}
__device__ __forceinline__ void mma8(float* c, const unsigned* a, const unsigned* b) {
    asm("mma.sync.aligned.m16n8k8.row.col.f32.tf32.tf32.f32 "
        "{%0,%1,%2,%3},{%4,%5,%6,%7},{%8,%9},{%0,%1,%2,%3};"
        : "+f"(c[0]), "+f"(c[1]), "+f"(c[2]), "+f"(c[3])
        : "r"(a[0]), "r"(a[1]), "r"(a[2]), "r"(a[3]), "r"(b[0]), "r"(b[1]));
}
__device__ __forceinline__ void cp16(unsigned dst, const void* src) {
    asm volatile("cp.async.cg.shared.global [%0], [%1], 16;" :: "r"(dst), "l"(src));
}
__device__ __forceinline__ void cp_commit() { asm volatile("cp.async.commit_group;"); }
__device__ __forceinline__ void cp_wait1()  { asm volatile("cp.async.wait_group 1;"); }
__device__ __forceinline__ void cp_wait0()  { asm volatile("cp.async.wait_group 0;"); }
__device__ __forceinline__ unsigned saddr(const void* p) {
    return (unsigned)__cvta_generic_to_shared(p);
}

// ---------------- RMSNorm ----------------
__global__ void rmsnorm_kernel(const float* __restrict__ x,
                               const float* __restrict__ g,
                               float* __restrict__ out)
{
    int row = blockIdx.x;
    int tid = threadIdx.x;
    const float4* xr = (const float4*)(x + (size_t)row * D_);
    float4 v = xr[tid];
    float ss = v.x * v.x + v.y * v.y + v.z * v.z + v.w * v.w;
    #pragma unroll
    for (int o = 16; o > 0; o >>= 1) ss += __shfl_xor_sync(0xffffffffu, ss, o);
    __shared__ float ws[8];
    if ((tid & 31) == 0) ws[tid >> 5] = ss;
    __syncthreads();
    if (tid < 8) {
        float t = ws[tid];
        #pragma unroll
        for (int o = 4; o > 0; o >>= 1) t += __shfl_xor_sync(0xffu, t, o);
        if (tid == 0) ws[0] = t;
    }
    __syncthreads();
    float scale = rsqrtf(ws[0] * (1.0f / (float)D_) + 1e-6f);
    float4 gv = ((const float4*)g)[tid];
    float4 o;
    o.x = v.x * scale * gv.x;
    o.y = v.y * scale * gv.y;
    o.z = v.z * scale * gv.z;
    o.w = v.w * scale * gv.w;
    ((float4*)(out + (size_t)row * D_))[tid] = o;
}

// ---------------- sinusoid table ----------------
__global__ void sinusoid_kernel()
{
    __shared__ double fd[512];
    int tid = threadIdx.x;
    int w0 = blockIdx.x * 64;
    for (int i = tid; i < 512; i += 256)
        fd[i] = exp(-(double)i * (9.210340371976184 / 512.0));
    __syncthreads();
    for (int e = tid; e < 64 * 512; e += 256) {
        int w = w0 + (e >> 9);
        int i = e & 511;
        int p = (W_ - 1) - w;
        double ang = (double)p * fd[i];
        double t = ang * 0.15915494309189535;
        t -= floor(t);
        float th = (float)(t * 6.283185307179586);
        float s, c;
        sincosf(th, &s, &c);
        g_sin[(size_t)w * D_ + i]          = s;
        g_sin[(size_t)w * D_ + 512 + i]    = c;
    }
}

// ---------------- corr[h][w] = (xl_v - xl_u) . R[w] ----------------
__global__ void corr_kernel(const float* __restrict__ xlu, const float* __restrict__ xlv)
{
    int w = 448 + blockIdx.x;         // 448..2559
    int hh = threadIdx.x >> 5, lane = threadIdx.x & 31;
    const float4 rv = *(const float4*)(g_r + (size_t)w * D_ + hh * K_ + lane * 4);
    const float4 uv = *(const float4*)(xlu + hh * K_ + lane * 4);
    const float4 vv = *(const float4*)(xlv + hh * K_ + lane * 4);
    float s = (vv.x - uv.x) * rv.x + (vv.y - uv.y) * rv.y
            + (vv.z - uv.z) * rv.z + (vv.w - uv.w) * rv.w;
    #pragma unroll
    for (int o = 16; o > 0; o >>= 1) s += __shfl_xor_sync(0xffffffffu, s, o);
    if (lane == 0) g_corr[(size_t)hh * W_ + w] = s;
}

// ---------------- pipelined 128x128 tf32 GEMM (NN), BK=32 ----------------
#define GEMM_SMEM ((2 * 128 * 36 + 2 * 32 * 132) * 4)
__global__ void __launch_bounds__(256) gemm_nn(
    const float* __restrict__ A,
    const float* __restrict__ B0, const float* __restrict__ B1, const float* __restrict__ B2,
    float* __restrict__ C0, float* __restrict__ C1, float* __restrict__ C2,
    int Nd, int Kd, float a0, float a1, float a2)
{
    const float* Bm; float* C; float alpha;
    if (blockIdx.z == 0)      { Bm = B0; C = C0; alpha = a0; }
    else if (blockIdx.z == 1) { Bm = B1; C = C1; alpha = a1; }
    else                      { Bm = B2; C = C2; alpha = a2; }

    extern __shared__ float smf[];
    float* sA = smf;
    float* sB = smf + 2 * 128 * 36;
    unsigned sAa = saddr(sA), sBa = saddr(sB);

    int tid = threadIdx.x;
    int lane = tid & 31, wid = tid >> 5;
    int wr = wid >> 1, wc = wid & 1;
    int qr = lane >> 2, qc = lane & 3;
    int m0 = blockIdx.y * 128, n0 = blockIdx.x * 128;
    int NIT = Kd >> 5;

    float acc[2][8][4];
    #pragma unroll
    for (int i = 0; i < 2; i++)
        #pragma unroll
        for (int j = 0; j < 8; j++)
            #pragma unroll
            for (int l = 0; l < 4; l++) acc[i][j][l] = 0.f;

    auto load_tiles = [&](int st, int k0) {
        unsigned da = sAa + st * (128 * 36 * 4);
        unsigned db = sBa + st * (32 * 132 * 4);
        #pragma unroll
        for (int j = 0; j < 4; j++) {
            int id = tid + j * 256;
            int ra = id >> 3, ca = (id & 7) << 2;
            cp16(da + (ra * 36 + ca) * 4, A + (size_t)(m0 + ra) * Kd + k0 + ca);
            int rb = id >> 5, cb = (id & 31) << 2;
            cp16(db + (rb * 132 + cb) * 4, Bm + (size_t)(k0 + rb) * Nd + n0 + cb);
        }
    };

    load_tiles(0, 0); cp_commit();

    for (int it = 0; it < NIT; it++) {
        int st = it & 1;
        if (it + 1 < NIT) { load_tiles(st ^ 1, (it + 1) << 5); cp_commit(); cp_wait1(); }
        else cp_wait0();
        __syncthreads();
        const float* cA = sA + st * (128 * 36);
        const float* cB = sB + st * (32 * 132);
        #pragma unroll
        for (int ks = 0; ks < 4; ks++) {
            const int kk = ks * 8;
            unsigned a[2][4], bf[8][2];
            #pragma unroll
            for (int mt = 0; mt < 2; mt++) {
                int r = wr * 32 + mt * 16 + qr;
                a[mt][0] = tf32cvt(cA[r * 36 + kk + qc]);
                a[mt][1] = tf32cvt(cA[(r + 8) * 36 + kk + qc]);
                a[mt][2] = tf32cvt(cA[r * 36 + kk + qc + 4]);
                a[mt][3] = tf32cvt(cA[(r + 8) * 36 + kk + qc + 4]);
            }
            #pragma unroll
            for (int nt = 0; nt < 8; nt++) {
                int cn = wc * 64 + nt * 8 + qr;
                bf[nt][0] = tf32cvt(cB[(kk + qc) * 132 + cn]);
                bf[nt][1] = tf32cvt(cB[(kk + qc + 4) * 132 + cn]);
            }
            #pragma unroll
            for (int mt = 0; mt < 2; mt++)
                #pragma unroll
                for (int nt = 0; nt < 8; nt++)
                    mma8(acc[mt][nt], a[mt], bf[nt]);
        }
        __syncthreads();
    }

    #pragma unroll
    for (int mt = 0; mt < 2; mt++) {
        int r = m0 + wr * 32 + mt * 16 + qr;
        #pragma unroll
        for (int nt = 0; nt < 8; nt++) {
            int col = n0 + wc * 64 + nt * 8 + qc * 2;
            *(float2*)(C + (size_t)r * Nd + col) =
                make_float2(acc[mt][nt][0] * alpha, acc[mt][nt][1] * alpha);
            *(float2*)(C + (size_t)(r + 8) * Nd + col) =
                make_float2(acc[mt][nt][2] * alpha, acc[mt][nt][3] * alpha);
        }
    }
}

// ---------------- fused banded flash attention (bd computed in-tile) ----------------
// smem word layout:
//  Qs(u32)  [64*132] @0       (q/tau + xl_u, tf32)
//  Kf(f32) 2x[64*132] @8448
//  Vf(f32)  [64*136] @25344
//  Rr(f32)  [128*132] @34048   ring of R rows (slot = row & 127)
//  Ssm(f32) [64*68]  @50944
//  mrow/lrow/arow @55296
#define ATT_SMEM (55488 * 4)
__global__ void __launch_bounds__(256) attn_fused(
    const float* __restrict__ cacheK, const float* __restrict__ cacheV,
    const float* __restrict__ xlu, const int* __restrict__ posp)
{
    extern __shared__ unsigned smu[];
    unsigned* Qs = smu;
    float* Kf  = (float*)(smu + 8448);
    float* Vf  = (float*)(smu + 25344);
    float* Rr  = (float*)(smu + 34048);
    float* Ssm = (float*)(smu + 50944);
    float* mrow = (float*)(smu + 55296);
    float* lrow = mrow + 64;
    float* arow = lrow + 64;
    unsigned Ka = saddr(Kf), Va = saddr(Vf), Ra = saddr(Rr);

    int tid = threadIdx.x;
    int lane = tid & 31, wid = tid >> 5;
    int wr = wid >> 1, wc = wid & 1;
    int qr = lane >> 2, qc = lane & 3;
    int bh = blockIdx.y;
    int b = bh >> 3, h = bh & 7;
    int i0 = blockIdx.x * 64;
    int inval = M_ - posp[0]; if (inval < 0) inval = 0;
    const float* rbase = g_r + (size_t)h * K_;
    const float* corrbase = g_corr + (size_t)h * W_;

    auto load_k = [&](int kt, int st) {
        int j0 = i0 + kt * 64;
        unsigned kd = Ka + st * (64 * 132 * 4);
        #pragma unroll
        for (int j = 0; j < 8; j++) {
            int id = tid + j * 256;
            int r = id >> 5, c = (id & 31) << 2;
            int jj = j0 + r;
            const float* kp;
            if (jj < M_) kp = cacheK + ((size_t)bh * M_ + jj) * K_ + c;
            else         kp = g_k + ((size_t)(b * L_ + (jj - M_))) * D_ + h * K_ + c;
            cp16(kd + (r * 132 + c) * 4, kp);
        }
    };
    auto load_v = [&](int kt) {
        int j0 = i0 + kt * 64;
        #pragma unroll
        for (int j = 0; j < 8; j++) {
            int id = tid + j * 256;
            int r = id >> 5, c = (id & 31) << 2;
            int jj = j0 + r;
            const float* vp;
            if (jj < M_) vp = cacheV + ((size_t)bh * M_ + jj) * K_ + c;
            else         vp = g_v + ((size_t)(b * L_ + (jj - M_))) * D_ + h * K_ + c;
            cp16(Va + (r * 136 + c) * 4, vp);
        }
    };
    auto load_r64 = [&](int wstart) {
        #pragma unroll
        for (int j = 0; j < 8; j++) {
            int id = tid + j * 256;
            int r = id >> 5, c = (id & 31) << 2;
            int w = wstart + r;
            int slot = w & 127;
            int wc2 = w > (W_ - 1) ? (W_ - 1) : w;
            cp16(Ra + (slot * 132 + c) * 4, rbase + (size_t)wc2 * D_ + c);
        }
    };

    // ---- prologue: G0 = [K tile0, R rows 448..575] ----
    load_k(0, 0);
    #pragma unroll
    for (int j = 0; j < 16; j++) {    // 128 R rows
        int id = tid + j * 256;
        int r = id >> 5, c = (id & 31) << 2;
        int w = 448 + r;
        cp16(Ra + ((w & 127) * 132 + c) * 4, rbase + (size_t)w * D_ + c);
    }
    cp_commit();

    // Q tile (+ xl_u) -> tf32
    const float* qbase = g_q + ((size_t)(b * L_ + i0)) * D_ + h * K_;
    #pragma unroll
    for (int l = 0; l < 8; l++) {
        int idx = tid + l * 256;
        int r = idx >> 5, c = (idx & 31) << 2;
        float4 qv = *(const float4*)(qbase + (size_t)r * D_ + c);
        float4 uv = *(const float4*)(xlu + h * K_ + c);
        *(uint4*)&Qs[r * 132 + c] = make_uint4(
            tf32cvt(qv.x + uv.x), tf32cvt(qv.y + uv.y),
            tf32cvt(qv.z + uv.z), tf32cvt(qv.w + uv.w));
    }
    if (tid < 64) { mrow[tid] = -1e30f; lrow[tid] = 0.f; }

    float oacc[8][4];
    #pragma unroll
    for (int i = 0; i < 8; i++)
        #pragma unroll
        for (int j = 0; j < 4; j++) oacc[i][j] = 0.f;

    int srow = tid >> 2, sg = tid & 3;
    int r = wr * 16 + qr;

    __syncthreads();

    for (int kt = 0; kt < 33; kt++) {
        int st = kt & 1;
        int j0 = i0 + kt * 64;
        bool hasNext = (kt + 1 < 33);

        // group Ga: V(kt) [+ K(kt+1)]
        load_v(kt);
        if (hasNext) load_k(kt + 1, st ^ 1);
        cp_commit();

        // ensure K(kt) + full R window for kt are resident (only Ga may be pending)
        cp_wait1();
        __syncthreads();

        const float* cK = Kf + st * (64 * 132);

        // ---- unified mma: S = (Q+u)K^T  and  C = (Q+u)Rwin^T ----
        float s[4][4], cf[8][4];
        #pragma unroll
        for (int i = 0; i < 4; i++)
            #pragma unroll
            for (int j = 0; j < 4; j++) s[i][j] = 0.f;
        #pragma unroll
        for (int i = 0; i < 8; i++)
            #pragma unroll
            for (int j = 0; j < 4; j++) cf[i][j] = 0.f;

        int rslot[8];
        #pragma unroll
        for (int nt = 0; nt < 8; nt++) {
            int t = wc * 64 + nt * 8 + qr;
            rslot[nt] = (448 + 64 * kt + t) & 127;
        }

        #pragma unroll
        for (int ks = 0; ks < 16; ks++) {
            const int kk = ks * 8;
            unsigned a[4];
            a[0] = Qs[r * 132 + kk + qc];
            a[1] = Qs[(r + 8) * 132 + kk + qc];
            a[2] = Qs[r * 132 + kk + qc + 4];
            a[3] = Qs[(r + 8) * 132 + kk + qc + 4];
            unsigned bf[2];
            #pragma unroll
            for (int nt = 0; nt < 4; nt++) {
                int n = wc * 32 + nt * 8 + qr;
                bf[0] = tf32cvt(cK[n * 132 + kk + qc]);
                bf[1] = tf32cvt(cK[n * 132 + kk + qc + 4]);
                mma8(s[nt], a, bf);
            }
            #pragma unroll
            for (int nt = 0; nt < 8; nt++) {
                bf[0] = tf32cvt(Rr[rslot[nt] * 132 + kk + qc]);
                bf[1] = tf32cvt(Rr[rslot[nt] * 132 + kk + qc + 4]);
                mma8(cf[nt], a, bf);
            }
        }
        // Rr window for this tile fully consumed; all warps must pass before
        // the prefetch below can overwrite the lower 64 rows of the window.
        __syncthreads();

        // group Gr: prefetch next 64 R rows (overlaps softmax + P@V)
        if (hasNext) { load_r64(576 + 64 * kt); cp_commit(); }

        // ---- scatter bd: Ssm[ri][t-63+ri] = C[ri][t] + corr ----
        #pragma unroll
        for (int nt = 0; nt < 8; nt++) {
            int t0 = wc * 64 + nt * 8 + qc * 2;
            #pragma unroll
            for (int e = 0; e < 2; e++) {
                int t = t0 + e;
                int rabs = 448 + 64 * kt + t;
                int ci = rabs > (W_ - 1) ? (W_ - 1) : rabs;
                float cr = corrbase[ci];
                int cj0 = t - 63 + r;
                if (cj0 >= 0 && cj0 < 64) Ssm[r * 68 + cj0] = cf[nt][e] + cr;
                int cj1 = cj0 + 8;
                if (cj1 >= 0 && cj1 < 64) Ssm[(r + 8) * 68 + cj1] = cf[nt][e + 2] + cr;
            }
        }
        __syncthreads();

        // ---- add S + bd + mask ----
        {
            int gi0 = i0 + r, gi1 = gi0 + 8;
            #pragma unroll
            for (int nt = 0; nt < 4; nt++) {
                int cbase = wc * 32 + nt * 8 + qc * 2;
                #pragma unroll
                for (int e = 0; e < 2; e++) {
                    int cc = cbase + e;
                    int gj = j0 + cc;
                    int dd0 = gj - gi0, dd1 = gj - gi1;
                    float b0 = Ssm[r * 68 + cc];
                    float b1 = Ssm[(r + 8) * 68 + cc];
                    float v0 = (dd0 >= 0 && dd0 <= 2048 && gj >= inval) ? (s[nt][e] + b0) : -1e30f;
                    float v1 = (dd1 >= 0 && dd1 <= 2048 && gj >= inval) ? (s[nt][2 + e] + b1) : -1e30f;
                    Ssm[r * 68 + cc] = v0;
                    Ssm[(r + 8) * 68 + cc] = v1;
                }
            }
        }
        __syncthreads();

        // ---- online softmax ----
        {
            float* Sr = Ssm + srow * 68 + sg * 16;
            float mx = -1e30f;
            #pragma unroll
            for (int c2 = 0; c2 < 16; c2++) mx = fmaxf(mx, Sr[c2]);
            mx = fmaxf(mx, __shfl_xor_sync(0xffffffffu, mx, 1));
            mx = fmaxf(mx, __shfl_xor_sync(0xffffffffu, mx, 2));
            float mold = mrow[srow];
            float mnew = fmaxf(mold, mx);
            float sum = 0.f;
            #pragma unroll
            for (int c2 = 0; c2 < 16; c2++) {
                float p = __expf(Sr[c2] - mnew);
                ((unsigned*)Sr)[c2] = tf32cvt(p);
                sum += p;
            }
            sum += __shfl_xor_sync(0xffffffffu, sum, 1);
            sum += __shfl_xor_sync(0xffffffffu, sum, 2);
            if (sg == 0) {
                float alpha = __expf(mold - mnew);
                arow[srow] = alpha;
                lrow[srow] = lrow[srow] * alpha + sum;
                mrow[srow] = mnew;
            }
        }
        // V(kt) must be resident (only Gr may be pending)
        if (hasNext) cp_wait1(); else cp_wait0();
        __syncthreads();

        // ---- phase C: rescale + O += P @ V ----
        {
            float al0 = arow[r], al1 = arow[r + 8];
            #pragma unroll
            for (int nt = 0; nt < 8; nt++) {
                oacc[nt][0] *= al0; oacc[nt][1] *= al0;
                oacc[nt][2] *= al1; oacc[nt][3] *= al1;
            }
            const unsigned* Pu = (const unsigned*)Ssm;
            #pragma unroll
            for (int ks = 0; ks < 8; ks++) {
                const int kk = ks * 8;
                unsigned a[4], bf[8][2];
                a[0] = Pu[r * 68 + kk + qc];
                a[1] = Pu[(r + 8) * 68 + kk + qc];
                a[2] = Pu[r * 68 + kk + qc + 4];
                a[3] = Pu[(r + 8) * 68 + kk + qc + 4];
                #pragma unroll
                for (int nt = 0; nt < 8; nt++) {
                    int n = wc * 64 + nt * 8 + qr;
                    bf[nt][0] = tf32cvt(Vf[(kk + qc) * 136 + n]);
                    bf[nt][1] = tf32cvt(Vf[(kk + qc + 4) * 136 + n]);
                }
                #pragma unroll
                for (int nt = 0; nt < 8; nt++) mma8(oacc[nt], a, bf[nt]);
            }
        }
        __syncthreads();   // protect Vf + Ssm for next iteration
    }

    // epilogue
    {
        float inv0 = 1.0f / lrow[r];
        float inv1 = 1.0f / lrow[r + 8];
        float* o0 = g_wv + ((size_t)(b * L_ + i0 + r)) * D_ + h * K_;
        float* o1 = g_wv + ((size_t)(b * L_ + i0 + r + 8)) * D_ + h * K_;
        #pragma unroll
        for (int nt = 0; nt < 8; nt++) {
            int col = wc * 64 + nt * 8 + qc * 2;
            *(float2*)(o0 + col) = make_float2(oacc[nt][0] * inv0, oacc[nt][1] * inv0);
            *(float2*)(o1 + col) = make_float2(oacc[nt][2] * inv1, oacc[nt][3] * inv1);
        }
    }
}

// ---------------- launch ----------------
extern "C" void kernel_launch(void* const* d_in, const int* in_sizes, int n_in,
                              void* d_out, int out_size)
{
    const float* x      = (const float*)d_in[0];
    const int*   pos    = (const int*)  d_in[1];
    const float* cacheK = (const float*)d_in[2];
    const float* cacheV = (const float*)d_in[3];
    const float* g_rms  = (const float*)d_in[4];
    const float* Wq     = (const float*)d_in[5];
    const float* Wk     = (const float*)d_in[6];
    const float* Wv     = (const float*)d_in[7];
    const float* Wr     = (const float*)d_in[8];
    const float* xlu    = (const float*)d_in[9];
    const float* xlv    = (const float*)d_in[10];
    const float* Wo     = (const float*)d_in[11];
    float* out          = (float*)d_out;

    float *p_xt, *p_q, *p_k, *p_v, *p_sin, *p_r, *p_wv;
    cudaGetSymbolAddress((void**)&p_xt,  g_xt);
    cudaGetSymbolAddress((void**)&p_q,   g_q);
    cudaGetSymbolAddress((void**)&p_k,   g_k);
    cudaGetSymbolAddress((void**)&p_v,   g_v);
    cudaGetSymbolAddress((void**)&p_sin, g_sin);
    cudaGetSymbolAddress((void**)&p_r,   g_r);
    cudaGetSymbolAddress((void**)&p_wv,  g_wv);

    cudaFuncSetAttribute(gemm_nn,    cudaFuncAttributeMaxDynamicSharedMemorySize, GEMM_SMEM);
    cudaFuncSetAttribute(attn_fused, cudaFuncAttributeMaxDynamicSharedMemorySize, ATT_SMEM);

    const float inv_tau = 0.08838834764831845f; // 1/sqrt(128)

    // 1) RMSNorm
    rmsnorm_kernel<<<B_ * L_, 256>>>(x, g_rms, p_xt);

    // 2) fused Q/K/V projections
    gemm_nn<<<dim3(D_ / 128, (B_ * L_) / 128, 3), 256, GEMM_SMEM>>>(
        p_xt, Wq, Wk, Wv, p_q, p_k, p_v, D_, D_, inv_tau, 1.0f, 1.0f);

    // 3) positional keys R = sinusoid @ Wr (rows >= 384)
    sinusoid_kernel<<<W_ / 64, 256>>>();
    gemm_nn<<<dim3(D_ / 128, 17, 1), 256, GEMM_SMEM>>>(
        p_sin + (size_t)384 * D_, Wr, Wr, Wr,
        p_r + (size_t)384 * D_, p_r, p_r, D_, D_, 1.0f, 1.0f, 1.0f);

    // 4) corr vector
    corr_kernel<<<W_ - 448, 256>>>(xlu, xlv);

    // 5) fused banded flash attention (bd in-tile)
    attn_fused<<<dim3(L_ / 64, B_ * H_), 256, ATT_SMEM>>>(cacheK, cacheV, xlu, pos);

    // 6) output projection
    gemm_nn<<<dim3(D_ / 128, (B_ * L_) / 128, 1), 256, GEMM_SMEM>>>(
        p_wv, Wo, Wo, Wo, out, out, out, D_, D_, 1.0f, 1.0f, 1.0f);
}